// round 6
// baseline (speedup 1.0000x reference)
#include <cuda_runtime.h>
#include <cuda_fp16.h>

// 5-level db4 DWT, symmetric extension. fp16 smem cascade, fp32 math via
// packed f32x2 FMA. Per level: 4 outputs/thread from 2 aligned LDS.128;
// per-level ext offset c chosen (mod 8, via templated window OFF) so that
// interior cA stores are a single STS.64 when alignment permits.

#define NROWS 4096
#define NT    256

#define L0 4096
#define L1 2051
#define L2 1029
#define L3 518
#define L4 262
#define L5 134

#define O_APPROX 0
#define O_D5 (NROWS * L5)
#define O_D4 (O_D5 + NROWS * L5)
#define O_D3 (O_D4 + NROWS * L4)
#define O_D2 (O_D3 + NROWS * L3)
#define O_D1 (O_D2 + NROWS * L2)

// Reversed filters RF[r] = DEC[7-r]; y[j] = sum_r RF[r] * ext[2j+r]
#define RLO0  0.23037781330885523f
#define RLO1  0.7148465705525415f
#define RLO2  0.6308807679295904f
#define RLO3 -0.02798376941698385f
#define RLO4 -0.18703481171888114f
#define RLO5  0.030841381835986965f
#define RLO6  0.032883011666982945f
#define RLO7 -0.010597401784997278f

#define RHI0 -0.010597401784997278f
#define RHI1 -0.032883011666982945f
#define RHI2  0.030841381835986965f
#define RHI3  0.18703481171888114f
#define RHI4 -0.02798376941698385f
#define RHI5 -0.6308807679295904f
#define RHI6  0.7148465705525415f
#define RHI7 -0.23037781330885523f

typedef unsigned long long u64;

__device__ __forceinline__ u64 f2pack(float x, float y) {
    u64 r; asm("mov.b64 %0, {%1, %2};" : "=l"(r) : "f"(x), "f"(y)); return r;
}
__device__ __forceinline__ u64 h2f2(unsigned int h) {
    __half2 hh = *reinterpret_cast<__half2*>(&h);
    float2 t = __half22float2(hh);
    return f2pack(t.x, t.y);
}
__device__ __forceinline__ u64 mul2(u64 a, u64 b) {
    u64 d; asm("mul.rn.f32x2 %0, %1, %2;" : "=l"(d) : "l"(a), "l"(b)); return d;
}
__device__ __forceinline__ u64 fma2(u64 a, u64 b, u64 c) {
    u64 d; asm("fma.rn.f32x2 %0, %1, %2, %3;" : "=l"(d) : "l"(a), "l"(b), "l"(c)); return d;
}
__device__ __forceinline__ float hsum(u64 v) {
    float r;
    asm("{.reg .f32 a, b; mov.b64 {a, b}, %1; add.f32 %0, a, b;}"
        : "=f"(r) : "l"(v));
    return r;
}

// Choose window offset (off) / ext base (c) for level k so that the PREVIOUS
// level's interior cA store is maximally aligned. Load needs c = 8+((2sk+2off)&7).
__device__ __forceinline__ void pickc(int sk, int sp, int& off, int& c, int& cb,
                                      int& smode) {
    const int v0 = 2 * sk,     ca = 8 + (v0 & 7), a0 = (ca + 6 - sp) & 3;
    const int v1 = 2 * sk + 2, cbv = 8 + (v1 & 7), a1 = (cbv + 6 - sp) & 3;
    const int r0 = (a0 == 0) ? 0 : ((a0 == 2) ? 1 : 2);
    const int r1 = (a1 == 0) ? 0 : ((a1 == 2) ? 1 : 2);
    if (r1 < r0) { off = 1; c = cbv; cb = cbv - v1; smode = (a1 == 0) ? 0 : ((a1 == 2) ? 2 : 1); }
    else         { off = 0; c = ca;  cb = ca - v0;  smode = (a0 == 0) ? 0 : ((a0 == 2) ? 2 : 1); }
}

// One level: M outputs. q: fp16 ext buffer, loads from q[cb + 8T] (aligned).
// w0 of thread T = word OFF of the 8 loaded words. j0 = 4T - sigma.
// cD -> fp32 gmem (STG.128 interior). !LAST: cA -> qn at cst=c_next+6 with
// smode (0: STS.64, 2: 2x STS.32, 1: scalar). LAST: cA -> fp32 gmem cAg.
template<int OFF, bool LAST>
__device__ __forceinline__ void lvl(const __half* __restrict__ q, int cb,
                                    int M, int sigma,
                                    __half* __restrict__ qn, int cst, int smode,
                                    float* __restrict__ cD,
                                    float* __restrict__ cAg, int tid) {
    const u64 CL0 = f2pack(RLO0, RLO1), CL1 = f2pack(RLO2, RLO3);
    const u64 CL2 = f2pack(RLO4, RLO5), CL3 = f2pack(RLO6, RLO7);
    const u64 CH0 = f2pack(RHI0, RHI1), CH1 = f2pack(RHI2, RHI3);
    const u64 CH2 = f2pack(RHI4, RHI5), CH3 = f2pack(RHI6, RHI7);

    const uint4* __restrict__ Q4 = reinterpret_cast<const uint4*>(q + cb);
    const int NB = (M + sigma + 3) >> 2;

    for (int T = tid; T < NB; T += NT) {
        const uint4 A = Q4[T];
        const uint4 B = Q4[T + 1];
        const unsigned int W[8] = {A.x, A.y, A.z, A.w, B.x, B.y, B.z, B.w};
        u64 F[7];
#pragma unroll
        for (int i = 0; i < 7; i++) F[i] = h2f2(W[i + OFF]);

        float lo[4], hi[4];
#pragma unroll
        for (int m = 0; m < 4; m++) {
            u64 sl = mul2(CL0, F[m]);
            sl = fma2(CL1, F[m + 1], sl);
            sl = fma2(CL2, F[m + 2], sl);
            sl = fma2(CL3, F[m + 3], sl);
            lo[m] = hsum(sl);
            u64 sh = mul2(CH0, F[m]);
            sh = fma2(CH1, F[m + 1], sh);
            sh = fma2(CH2, F[m + 2], sh);
            sh = fma2(CH3, F[m + 3], sh);
            hi[m] = hsum(sh);
        }

        const int j0 = 4 * T - sigma;
        const bool intD = (j0 >= 0) && (j0 + 4 <= M);
        if (intD) {
            *reinterpret_cast<float4*>(cD + j0) =
                make_float4(hi[0], hi[1], hi[2], hi[3]);
            if (LAST)
                *reinterpret_cast<float4*>(cAg + j0) =
                    make_float4(lo[0], lo[1], lo[2], lo[3]);
        } else {
#pragma unroll
            for (int m = 0; m < 4; m++) {
                const int j = j0 + m;
                if (j >= 0 && j < M) {
                    cD[j] = hi[m];
                    if (LAST) cAg[j] = lo[m];
                }
            }
        }

        if (!LAST) {
            const bool intA = intD && (j0 > 5) && (j0 + 3 < M - 8);
            if (intA) {
                if (smode == 0) {
                    __half2 p01 = __floats2half2_rn(lo[0], lo[1]);
                    __half2 p23 = __floats2half2_rn(lo[2], lo[3]);
                    uint2 v;
                    v.x = *reinterpret_cast<unsigned int*>(&p01);
                    v.y = *reinterpret_cast<unsigned int*>(&p23);
                    *reinterpret_cast<uint2*>(qn + cst + j0) = v;
                } else if (smode == 2) {
                    *reinterpret_cast<__half2*>(qn + cst + j0) =
                        __floats2half2_rn(lo[0], lo[1]);
                    *reinterpret_cast<__half2*>(qn + cst + j0 + 2) =
                        __floats2half2_rn(lo[2], lo[3]);
                } else {
#pragma unroll
                    for (int m = 0; m < 4; m++)
                        qn[cst + j0 + m] = __float2half_rn(lo[m]);
                }
            } else {
#pragma unroll
                for (int m = 0; m < 4; m++) {
                    const int j = j0 + m;
                    if (j < 0 || j >= M) continue;
                    const __half v = __float2half_rn(lo[m]);
                    qn[cst + j] = v;                          // interior
                    if (j <= 5)     qn[cst - 1 - j] = v;      // left mirror
                    if (j >= M - 8) qn[cst + 2 * M - 1 - j] = v; // right mirror
                }
            }
        }
    }
}

__global__ __launch_bounds__(NT)
void wavelet5_kernel(const float* __restrict__ x, float* __restrict__ out) {
    __shared__ __align__(16) __half IN16[4160]; // lvl1 in / lvl3 out / lvl4 in
    __shared__ __align__(16) __half A16[2112];  // lvl1 out / lvl2 in / lvl4 out / lvl5 in
    __shared__ __align__(16) __half B16[1088];  // lvl2 out / lvl3 in

    const int row = blockIdx.x;
    const int tid = threadIdx.x;

    const int s1 = (3 * row) & 3;   // L1 = 2051 ≡ 3 (mod 4)
    const int s2 = row & 3;         // L2 = 1029 ≡ 1
    const int s3 = (2 * row) & 3;   // L3,L4,L5 ≡ 2

    // Level 1: off forced so the input-stage STS.64 is aligned (c1 ≡ 2 mod 4).
    const int off1 = 1 - (s1 & 1);
    const int v1 = 2 * s1 + 2 * off1;
    const int c1 = 8 + (v1 & 7), cb1 = c1 - v1;

    int off2, c2, cb2, sm1; pickc(s2, s1, off2, c2, cb2, sm1);
    int off3, c3, cb3, sm2; pickc(s3, s2, off3, c3, cb3, sm2);
    int off4, c4, cb4, sm3; pickc(s3, s3, off4, c4, cb4, sm3);
    int off5, c5, cb5, sm4; pickc(s3, s3, off5, c5, cb5, sm4);

    const float* __restrict__ xr = x + (size_t)row * L0;

    // Input stage: ext[i] = IN16[c1 + i]; one float4 -> one STS.64 of 4 halfs.
    {
        const float4* __restrict__ x4 = reinterpret_cast<const float4*>(xr);
        __half* __restrict__ base = IN16 + c1 + 6;
#pragma unroll 4
        for (int u = tid; u < L0 / 4; u += NT) {
            const float4 v = x4[u];
            __half2 p01 = __floats2half2_rn(v.x, v.y);
            __half2 p23 = __floats2half2_rn(v.z, v.w);
            uint2 w;
            w.x = *reinterpret_cast<unsigned int*>(&p01);
            w.y = *reinterpret_cast<unsigned int*>(&p23);
            *reinterpret_cast<uint2*>(base + 4 * u) = w;
        }
        if (tid < 6) {
            IN16[c1 + tid] = __float2half_rn(xr[5 - tid]);          // left ext
        } else if (tid < 14) {
            const int t = tid - 6;
            IN16[c1 + L0 + 6 + t] = __float2half_rn(xr[L0 - 1 - t]); // right ext
        }
    }
    __syncthreads();

    float* __restrict__ d1 = out + O_D1 + (size_t)row * L1;
    float* __restrict__ d2 = out + O_D2 + (size_t)row * L2;
    float* __restrict__ d3 = out + O_D3 + (size_t)row * L3;
    float* __restrict__ d4 = out + O_D4 + (size_t)row * L4;
    float* __restrict__ d5 = out + O_D5 + (size_t)row * L5;
    float* __restrict__ ap = out + O_APPROX + (size_t)row * L5;

    if (off1) lvl<1, false>(IN16, cb1, L1, s1, A16, c2 + 6, sm1, d1, nullptr, tid);
    else      lvl<0, false>(IN16, cb1, L1, s1, A16, c2 + 6, sm1, d1, nullptr, tid);
    __syncthreads();
    if (off2) lvl<1, false>(A16, cb2, L2, s2, B16, c3 + 6, sm2, d2, nullptr, tid);
    else      lvl<0, false>(A16, cb2, L2, s2, B16, c3 + 6, sm2, d2, nullptr, tid);
    __syncthreads();
    if (off3) lvl<1, false>(B16, cb3, L3, s3, IN16, c4 + 6, sm3, d3, nullptr, tid);
    else      lvl<0, false>(B16, cb3, L3, s3, IN16, c4 + 6, sm3, d3, nullptr, tid);
    __syncthreads();
    if (off4) lvl<1, false>(IN16, cb4, L4, s3, A16, c5 + 6, sm4, d4, nullptr, tid);
    else      lvl<0, false>(IN16, cb4, L4, s3, A16, c5 + 6, sm4, d4, nullptr, tid);
    __syncthreads();
    if (off5) lvl<1, true>(A16, cb5, L5, s3, nullptr, 0, 0, d5, ap, tid);
    else      lvl<0, true>(A16, cb5, L5, s3, nullptr, 0, 0, d5, ap, tid);
}

extern "C" void kernel_launch(void* const* d_in, const int* in_sizes, int n_in,
                              void* d_out, int out_size) {
    const float* x = (const float*)d_in[0];
    float* out = (float*)d_out;
    (void)in_sizes; (void)n_in; (void)out_size;
    wavelet5_kernel<<<NROWS, NT>>>(x, out);
}